// round 11
// baseline (speedup 1.0000x reference)
#include <cuda_runtime.h>

#define BB 512
#define SS 1024
#define TT 64
#define CTAS BB                  // one batch per 64-thread CTA (2 warps)

#define LOG2E 1.4426950408889634f
#define LN2   0.6931471805599453f
#define LN64  4.1588830833596715f

// Precomputed shifted transition exponentials (step-invariant).
__device__ float g_E[TT * TT];     // E'[t][k] = exp(trans[t][k] - rowmax[t])
__device__ float g_rmax[TT];       // rowmax[t] = max_k trans[t][k]

// ---------------------------------------------------------------------------
// prep: E' = exp(trans - rowmax) ; one block per row t, 64 threads (2 warps)
// ---------------------------------------------------------------------------
__global__ void crf_prep_kernel(const float* __restrict__ trans) {
    int t = blockIdx.x;
    int k = threadIdx.x;
    float x = trans[t * TT + k];

    __shared__ float sm[2];
    int i = __float_as_int(x);
    i = (i >= 0) ? i : (i ^ 0x7FFFFFFF);
    i = __reduce_max_sync(0xFFFFFFFFu, i);
    float wm = __int_as_float((i >= 0) ? i : (i ^ 0x7FFFFFFF));
    if ((k & 31) == 0) sm[k >> 5] = wm;
    __syncthreads();
    float rmax = fmaxf(sm[0], sm[1]);

    g_E[t * TT + k] = __expf(x - rmax);
    if (k == 0) g_rmax[t] = rmax;
}

// ---------------------------------------------------------------------------
// packed f32x2 helpers (Blackwell packed fp32 pipe; PTX-only)
// ---------------------------------------------------------------------------
typedef unsigned long long u64;

__device__ __forceinline__ u64 pk2(float lo, float hi) {
    u64 r; asm("mov.b64 %0, {%1, %2};" : "=l"(r) : "f"(lo), "f"(hi)); return r;
}
__device__ __forceinline__ void upk2(float& lo, float& hi, u64 v) {
    asm("mov.b64 {%0, %1}, %2;" : "=f"(lo), "=f"(hi) : "l"(v));
}
__device__ __forceinline__ u64 fma2(u64 a, u64 b, u64 c) {
    u64 d; asm("fma.rn.f32x2 %0, %1, %2, %3;" : "=l"(d) : "l"(a), "l"(b), "l"(c));
    return d;
}
__device__ __forceinline__ u64 add2(u64 a, u64 b) {
    u64 d; asm("add.rn.f32x2 %0, %1, %2;" : "=l"(d) : "l"(a), "l"(b));
    return d;
}
__device__ __forceinline__ float ex2(float x) {
    float r; asm("ex2.approx.ftz.f32 %0, %1;" : "=f"(r) : "f"(x)); return r;
}
__device__ __forceinline__ float lg2(float x) {
    float r; asm("lg2.approx.ftz.f32 %0, %1;" : "=f"(r) : "f"(x)); return r;
}

// monotone float<->ordered-int map for REDUX-based float max (general floats)
__device__ __forceinline__ int fmap(float x) {
    int i = __float_as_int(x);
    return (i >= 0) ? i : (i ^ 0x7FFFFFFF);
}
__device__ __forceinline__ float funmap(int i) {
    return __int_as_float((i >= 0) ? i : (i ^ 0x7FFFFFFF));
}

// ---------------------------------------------------------------------------
// main scan: ONE BATCH PER 64-THREAD CTA (2 warps); each lane owns ONE state.
//
// Exp-domain chain (as R10): P[t] = 2^(A[t] - s) carried directly;
//   P_next = S * G, S = dot(E'[t,:], P), G = 2^(F - s') computed off-chain.
// Warp-scope maxes (maxP, maxfeat) are combined across the 2 warps through
// parity-double-buffered smem slots, consumed one step later (the shift
// schedule already tolerates that lag). One __syncthreads per step is the
// only cross-warp sync; it also drains the P STS (producer/consumer fence).
// ---------------------------------------------------------------------------
__global__ void __launch_bounds__(TT, 1) crf_scan_kernel(
    const float* __restrict__ feats,   // [B, S, T]
    const float* __restrict__ masks,   // [B, S]
    float* __restrict__ out)           // [B, T]
{
    const int t    = threadIdx.x;      // state 0..63
    const int w    = t >> 5;           // warp 0/1
    const int lane = t & 31;
    const int b    = blockIdx.x;

    __shared__ __align__(16) float vbuf[2][TT];  // P exchange, parity-buffered
    __shared__ float mfbuf[2][2];                // per-warp max feat, parity
    __shared__ float rpbuf[2][2];                // per-warp max P,   parity
    __shared__ float sm_tmp[2];

    // E' row for this lane's state t, packed as f32x2 pairs (32 u64 = 64 regs)
    u64 e[32];
    {
        const float4* rp = (const float4*)(g_E + t * TT);
#pragma unroll
        for (int j = 0; j < 16; j++) {
            float4 a = rp[j];
            e[2 * j]     = pk2(a.x, a.y);
            e[2 * j + 1] = pk2(a.z, a.w);
        }
    }
    const float rm = g_rmax[t];
    const float r2 = rm * LOG2E;       // row shift in log2 domain

    // maxT = max_t rmax[t] across the whole CTA
    float wmT = funmap(__reduce_max_sync(0xFFFFFFFFu, fmap(rm)));
    if (lane == 0) sm_tmp[w] = wmT;
    __syncthreads();
    const float maxT = fmaxf(sm_tmp[0], sm_tmp[1]);
    const float Rp2 = (maxT + LN64) * LOG2E;   // per-step growth bound const

    const float* fptr = feats + (long)b * SS * TT;
    const float* mptr = masks + (long)b * SS;

    // alpha0 = feats[:, 0, :]  (log2 domain, off-chain shadow)
    float A = fptr[t] * LOG2E;

    // distance-2 feats/mask prefetch (one value per lane now)
    float fA = __ldg(fptr + TT + t);
    float mA = __ldg(mptr + 1);
    float fB = __ldg(fptr + 2 * TT + t);
    float mB = __ldg(mptr + 2);

    // s_1 = exact CTA max of A_0
    {
        float wm = funmap(__reduce_max_sync(0xFFFFFFFFu, fmap(A)));
        if (lane == 0) sm_tmp[w] = wm;
    }
    __syncthreads();
    float sC = fmaxf(sm_tmp[0], sm_tmp[1]);

    // P_1 = 2^(A_0 - s_1)
    float P = ex2(A - sC);

    // seed parity-slot 0: max P_1 per warp; max feat_1 per warp
    {
        int rp = __reduce_max_sync(0xFFFFFFFFu, __float_as_int(P)); // P >= 0
        if (lane == 0) rpbuf[0][w] = __int_as_float(rp);
        float wmf = funmap(__reduce_max_sync(0xFFFFFFFFu, fmap(fA)));
        if (lane == 0) mfbuf[0][w] = wmf;
    }
    // (visibility of these seeds is ensured by the loop-head barrier)

    int p = 0;
#pragma unroll 2
    for (int i = 1; i < SS; i++) {
        // ---- chain head: publish P, barrier (drains STS) -----------------
        vbuf[p][t] = P;
        __syncthreads();

        // ---- off-chain: prefetch i+2 (branch-free, clamped) --------------
        const int ip2 = (i + 2 < SS) ? (i + 2) : (SS - 1);
        float fC = __ldg(fptr + ip2 * TT + t);
        float mC = __ldg(mptr + ip2);

        // ---- off-chain: shift maintenance (combined from parity slot p) --
        float maxPc = fmaxf(rpbuf[p][0], rpbuf[p][1]);   // max P_i (CTA)
        float mf    = fmaxf(mfbuf[p][0], mfbuf[p][1]);   // max feat_i (CTA)
        float maxA  = sC + lg2(maxPc);                   // exact max A_{i-1}
        float sN = maxA + fmaxf(0.0f, fmaf(mf, LOG2E, Rp2));
        float F  = fmaf(fA, LOG2E, sC + r2);
        float G  = ex2(F - sN);
        float H  = ex2(sC - sN);

        // ---- off-chain: publish warp-max of feat_{i+1} for next iter -----
        {
            float wmf = funmap(__reduce_max_sync(0xFFFFFFFFu, fmap(fB)));
            if (lane == 0) mfbuf[p ^ 1][w] = wmf;
        }

        // ---- critical chain: dot S = sum_k E'[t][k] * P[k] ---------------
        const ulonglong2* vv = (const ulonglong2*)vbuf[p];
        u64 Aa = pk2(0.f, 0.f), Ab = Aa, Ac = Aa, Ad = Aa;
#pragma unroll
        for (int j = 0; j < 4; j++) {
            ulonglong2 q0 = vv[4 * j];
            ulonglong2 q1 = vv[4 * j + 1];
            ulonglong2 q2 = vv[4 * j + 2];
            ulonglong2 q3 = vv[4 * j + 3];
            Aa = fma2(q0.x, e[8 * j],     Aa);
            Ab = fma2(q0.y, e[8 * j + 1], Ab);
            Ac = fma2(q1.x, e[8 * j + 2], Ac);
            Ad = fma2(q1.y, e[8 * j + 3], Ad);
            Aa = fma2(q2.x, e[8 * j + 4], Aa);
            Ab = fma2(q2.y, e[8 * j + 5], Ab);
            Ac = fma2(q3.x, e[8 * j + 6], Ac);
            Ad = fma2(q3.y, e[8 * j + 7], Ad);
        }
        float slo, shi;
        upk2(slo, shi, add2(add2(Aa, Ab), add2(Ac, Ad)));
        float S = slo + shi;

        // ---- chain tail: next P (1 FMUL + select; no MUFU) ---------------
        bool msk = (mA != 0.0f);
        P = msk ? S * G : P * H;

        // ---- off-chain: publish warp-max of P_{i+1} for next iter --------
        {
            int rp = __reduce_max_sync(0xFFFFFFFFu, __float_as_int(P));
            if (lane == 0) rpbuf[p ^ 1][w] = __int_as_float(rp);
        }

        // ---- off-chain: log-domain shadow of alpha (output path) ---------
        float n = F + lg2(S);
        A = fmaf(mA, n - A, A);

        // rotate shift + prefetch registers
        sC = sN;
        fA = fB; mA = mB;
        fB = fC; mB = mC;
        p ^= 1;
    }

    // back to natural log (from the exact log-domain shadow)
    out[b * TT + t] = A * LN2;
}

// ---------------------------------------------------------------------------
// launch
// ---------------------------------------------------------------------------
extern "C" void kernel_launch(void* const* d_in, const int* in_sizes, int n_in,
                              void* d_out, int out_size) {
    const float* feats = (const float*)d_in[0];  // [512, 1024, 64]
    const float* masks = (const float*)d_in[1];  // [512, 1024]
    const float* trans = (const float*)d_in[2];  // [64, 64]
    float* out = (float*)d_out;                  // [512, 64]

    crf_prep_kernel<<<TT, TT>>>(trans);
    crf_scan_kernel<<<CTAS, TT>>>(feats, masks, out);
}

// round 12
// speedup vs baseline: 1.3839x; 1.3839x over previous
#include <cuda_runtime.h>

#define BB 512
#define SS 1024
#define TT 64
#define WARPS_PER_CTA 4
#define CTAS (BB / WARPS_PER_CTA)   // 128

#define LOG2E 1.4426950408889634f
#define LN2   0.6931471805599453f
#define LN64  4.1588830833596715f

// Precomputed shifted transition exponentials (step-invariant).
__device__ float g_E[TT * TT];     // E'[t][k] = exp(trans[t][k] - rowmax[t])
__device__ float g_rmax[TT];       // rowmax[t] = max_k trans[t][k]

// ---------------------------------------------------------------------------
// prep: E' = exp(trans - rowmax) ; one block per row t, 64 threads (2 warps)
// ---------------------------------------------------------------------------
__global__ void crf_prep_kernel(const float* __restrict__ trans) {
    int t = blockIdx.x;
    int k = threadIdx.x;
    float x = trans[t * TT + k];

    __shared__ float sm[2];
    int i = __float_as_int(x);
    i = (i >= 0) ? i : (i ^ 0x7FFFFFFF);
    i = __reduce_max_sync(0xFFFFFFFFu, i);
    float wm = __int_as_float((i >= 0) ? i : (i ^ 0x7FFFFFFF));
    if ((k & 31) == 0) sm[k >> 5] = wm;
    __syncthreads();
    float rmax = fmaxf(sm[0], sm[1]);

    g_E[t * TT + k] = __expf(x - rmax);
    if (k == 0) g_rmax[t] = rmax;
}

// ---------------------------------------------------------------------------
// packed f32x2 helpers (Blackwell packed fp32 pipe; PTX-only)
// ---------------------------------------------------------------------------
typedef unsigned long long u64;

__device__ __forceinline__ u64 pk2(float lo, float hi) {
    u64 r; asm("mov.b64 %0, {%1, %2};" : "=l"(r) : "f"(lo), "f"(hi)); return r;
}
__device__ __forceinline__ void upk2(float& lo, float& hi, u64 v) {
    asm("mov.b64 {%0, %1}, %2;" : "=f"(lo), "=f"(hi) : "l"(v));
}
__device__ __forceinline__ u64 fma2(u64 a, u64 b, u64 c) {
    u64 d; asm("fma.rn.f32x2 %0, %1, %2, %3;" : "=l"(d) : "l"(a), "l"(b), "l"(c));
    return d;
}
__device__ __forceinline__ u64 add2(u64 a, u64 b) {
    u64 d; asm("add.rn.f32x2 %0, %1, %2;" : "=l"(d) : "l"(a), "l"(b));
    return d;
}
__device__ __forceinline__ float ex2(float x) {
    float r; asm("ex2.approx.ftz.f32 %0, %1;" : "=f"(r) : "f"(x)); return r;
}
__device__ __forceinline__ float lg2(float x) {
    float r; asm("lg2.approx.ftz.f32 %0, %1;" : "=f"(r) : "f"(x)); return r;
}

// monotone float<->ordered-int map for REDUX-based float max (general floats)
__device__ __forceinline__ int fmap(float x) {
    int i = __float_as_int(x);
    return (i >= 0) ? i : (i ^ 0x7FFFFFFF);
}
__device__ __forceinline__ float funmap(int i) {
    return __int_as_float((i >= 0) ? i : (i ^ 0x7FFFFFFF));
}

// ---------------------------------------------------------------------------
// main scan: one warp per batch; lane owns ADJACENT states (2l, 2l+1).
//
// Exp-domain chain (as R10): P[t] = 2^(A[t] - s) carried directly;
//   P_next = S * G, S = dot(E'[t,:], P), G = 2^(F - s') computed off-chain.
// Output path: (F, S) of the last masked step are LATCHED per state (4 FSELs
// per step); A = F + lg2(S) evaluated once after the loop. No per-step
// shadow, no per-step __syncwarp (same-warp STS->LDS, converged straight-line
// code; parity double-buffer prevents WAR).
// ---------------------------------------------------------------------------
__global__ void __launch_bounds__(WARPS_PER_CTA * 32, 1) crf_scan_kernel(
    const float* __restrict__ feats,   // [B, S, T]
    const float* __restrict__ masks,   // [B, S]
    float* __restrict__ out)           // [B, T]
{
    const int wid  = threadIdx.x >> 5;
    const int lane = threadIdx.x & 31;
    const int b    = blockIdx.x * WARPS_PER_CTA + wid;
    const int t0 = 2 * lane, t1 = 2 * lane + 1;

    // per-warp double-buffered P exchange (broadcast reads -> conflict-free)
    __shared__ __align__(16) float vbuf[WARPS_PER_CTA][2][TT];

    // E' rows for this lane's two states, packed as f32x2 pairs over k
    u64 e0[32], e1[32];
    {
        const float4* r0p = (const float4*)(g_E + t0 * TT);
        const float4* r1p = (const float4*)(g_E + t1 * TT);
#pragma unroll
        for (int j = 0; j < 16; j++) {
            float4 a = r0p[j];
            e0[2 * j]     = pk2(a.x, a.y);
            e0[2 * j + 1] = pk2(a.z, a.w);
            float4 c = r1p[j];
            e1[2 * j]     = pk2(c.x, c.y);
            e1[2 * j + 1] = pk2(c.z, c.w);
        }
    }
    const float rm0 = g_rmax[t0];
    const float rm1 = g_rmax[t1];
    const float r20 = rm0 * LOG2E;   // row shift in log2 domain
    const float r21 = rm1 * LOG2E;

    // Rp2 = (max_{t,k} trans + ln 64) * log2e  -- per-step growth bound const.
    const float maxT = funmap(__reduce_max_sync(0xFFFFFFFFu,
                              fmap(fmaxf(rm0, rm1))));
    const float Rp2 = (maxT + LN64) * LOG2E;

    const float* fptr = feats + (long)b * SS * TT;
    const float* mptr = masks + (long)b * SS;

    // alpha0 = feats[:, 0, :]  (log2 domain)
    float2 a00 = *(const float2*)(fptr + t0);
    float A0 = a00.x * LOG2E;
    float A1 = a00.y * LOG2E;

    // output latches: A_out = Flat + lg2(Slat); init encodes alpha0
    float Flat0 = A0, Flat1 = A1;
    float Slat0 = 1.0f, Slat1 = 1.0f;

    // distance-2 feats/mask prefetch (paired LDG.64 now)
    float2 fA = __ldg((const float2*)(fptr + TT + t0));
    float  mA = __ldg(mptr + 1);
    float2 fB = __ldg((const float2*)(fptr + 2 * TT + t0));
    float  mB = __ldg(mptr + 2);

    // s_1 = exact warp max of A_0 ; P = 2^(A_0 - s_1)
    float sC = funmap(__reduce_max_sync(0xFFFFFFFFu, fmap(fmaxf(A0, A1))));
    float P0 = ex2(A0 - sC);
    float P1 = ex2(A1 - sC);
    // REDUX over positive P: int compare == float compare for x >= 0
    int redP = __reduce_max_sync(0xFFFFFFFFu, __float_as_int(fmaxf(P0, P1)));

    int p = 0;
#pragma unroll 2
    for (int i = 1; i < SS; i++) {
        // ---- chain head: publish P pair (one STS.64) ---------------------
        float* vb = vbuf[wid][p];
        *(float2*)(vb + t0) = make_float2(P0, P1);
        asm volatile("" ::: "memory");   // compiler barrier: no LDS hoist

        // ---- off-chain: shift maintenance --------------------------------
        // maxA_{i-1} = s_i + log2(max P_i)   (redP from previous step)
        float maxA = sC + lg2(__int_as_float(redP));
        float mf = funmap(__reduce_max_sync(0xFFFFFFFFu,
                          fmap(fmaxf(fA.x, fA.y))));
        float sN = maxA + fmaxf(0.0f, fmaf(mf, LOG2E, Rp2));
        float F0 = fmaf(fA.x, LOG2E, sC + r20);
        float F1 = fmaf(fA.y, LOG2E, sC + r21);
        float G0 = ex2(F0 - sN);
        float G1 = ex2(F1 - sN);
        float H  = ex2(sC - sN);

        // ---- off-chain: prefetch i+2 (clamped, branch-free) --------------
        int ip2 = i + 2; ip2 = (ip2 < SS) ? ip2 : (SS - 1);
        float2 fC = __ldg((const float2*)(fptr + ip2 * TT + t0));
        float  mC = __ldg(mptr + ip2);

        // ---- critical chain: dot S = sum_k E'[t][k] * P[k] ---------------
        const ulonglong2* vv = (const ulonglong2*)vb;
        u64 Aa0 = pk2(0.f, 0.f), Aa1 = Aa0, Bb0 = Aa0, Bb1 = Aa0;
#pragma unroll
        for (int j = 0; j < 16; j++) {
            ulonglong2 q = vv[j];
            Aa0 = fma2(q.x, e0[2 * j],     Aa0);
            Aa1 = fma2(q.y, e0[2 * j + 1], Aa1);
            Bb0 = fma2(q.x, e1[2 * j],     Bb0);
            Bb1 = fma2(q.y, e1[2 * j + 1], Bb1);
        }
        float s0lo, s0hi, s1lo, s1hi;
        upk2(s0lo, s0hi, add2(Aa0, Aa1));
        upk2(s1lo, s1hi, add2(Bb0, Bb1));
        float S0 = s0lo + s0hi;
        float S1 = s1lo + s1hi;

        // ---- chain tail: next P (1 FMUL + select; no MUFU) ---------------
        bool msk = (mA != 0.0f);
        P0 = msk ? S0 * G0 : P0 * H;
        P1 = msk ? S1 * G1 : P1 * H;
        redP = __reduce_max_sync(0xFFFFFFFFu, __float_as_int(fmaxf(P0, P1)));

        // ---- off-chain: latch (F,S) on masked steps (output path) --------
        Flat0 = msk ? F0 : Flat0;
        Flat1 = msk ? F1 : Flat1;
        Slat0 = msk ? S0 : Slat0;
        Slat1 = msk ? S1 : Slat1;

        // rotate shift + prefetch registers
        sC = sN;
        fA = fB; mA = mB;
        fB = fC; mB = mC;
        p ^= 1;
    }

    // A = Flat + lg2(Slat), back to natural log (2 MUFU total, post-loop)
    float2 o;
    o.x = (Flat0 + lg2(Slat0)) * LN2;
    o.y = (Flat1 + lg2(Slat1)) * LN2;
    *(float2*)(out + b * TT + t0) = o;
}

// ---------------------------------------------------------------------------
// launch
// ---------------------------------------------------------------------------
extern "C" void kernel_launch(void* const* d_in, const int* in_sizes, int n_in,
                              void* d_out, int out_size) {
    const float* feats = (const float*)d_in[0];  // [512, 1024, 64]
    const float* masks = (const float*)d_in[1];  // [512, 1024]
    const float* trans = (const float*)d_in[2];  // [64, 64]
    float* out = (float*)d_out;                  // [512, 64]

    crf_prep_kernel<<<TT, TT>>>(trans);
    crf_scan_kernel<<<CTAS, WARPS_PER_CTA * 32>>>(feats, masks, out);
}

// round 14
// speedup vs baseline: 1.5219x; 1.0997x over previous
#include <cuda_runtime.h>

#define BB 512
#define SS 1024
#define TT 64
#define WARPS_PER_CTA 4
#define CTAS (BB / WARPS_PER_CTA)   // 128

#define LOG2E 1.4426950408889634f
#define LN2   0.6931471805599453f
#define LN64  4.1588830833596715f

// Precomputed shifted transition exponentials (step-invariant).
__device__ float g_E[TT * TT];     // E'[t][k] = exp(trans[t][k] - rowmax[t])
__device__ float g_rmax[TT];       // rowmax[t] = max_k trans[t][k]

// ---------------------------------------------------------------------------
// prep: E' = exp(trans - rowmax) ; one block per row t, 64 threads (2 warps)
// ---------------------------------------------------------------------------
__global__ void crf_prep_kernel(const float* __restrict__ trans) {
    int t = blockIdx.x;
    int k = threadIdx.x;
    float x = trans[t * TT + k];

    __shared__ float sm[2];
    int i = __float_as_int(x);
    i = (i >= 0) ? i : (i ^ 0x7FFFFFFF);
    i = __reduce_max_sync(0xFFFFFFFFu, i);
    float wm = __int_as_float((i >= 0) ? i : (i ^ 0x7FFFFFFF));
    if ((k & 31) == 0) sm[k >> 5] = wm;
    __syncthreads();
    float rmax = fmaxf(sm[0], sm[1]);

    g_E[t * TT + k] = __expf(x - rmax);
    if (k == 0) g_rmax[t] = rmax;
}

// ---------------------------------------------------------------------------
// packed f32x2 helpers (Blackwell packed fp32 pipe; PTX-only)
// ---------------------------------------------------------------------------
typedef unsigned long long u64;

__device__ __forceinline__ u64 pk2(float lo, float hi) {
    u64 r; asm("mov.b64 %0, {%1, %2};" : "=l"(r) : "f"(lo), "f"(hi)); return r;
}
__device__ __forceinline__ void upk2(float& lo, float& hi, u64 v) {
    asm("mov.b64 {%0, %1}, %2;" : "=f"(lo), "=f"(hi) : "l"(v));
}
__device__ __forceinline__ u64 fma2(u64 a, u64 b, u64 c) {
    u64 d; asm("fma.rn.f32x2 %0, %1, %2, %3;" : "=l"(d) : "l"(a), "l"(b), "l"(c));
    return d;
}
__device__ __forceinline__ u64 add2(u64 a, u64 b) {
    u64 d; asm("add.rn.f32x2 %0, %1, %2;" : "=l"(d) : "l"(a), "l"(b));
    return d;
}
__device__ __forceinline__ float ex2(float x) {
    float r; asm("ex2.approx.ftz.f32 %0, %1;" : "=f"(r) : "f"(x)); return r;
}
__device__ __forceinline__ float lg2(float x) {
    float r; asm("lg2.approx.ftz.f32 %0, %1;" : "=f"(r) : "f"(x)); return r;
}

// monotone float<->ordered-int map for REDUX-based float max (general floats)
__device__ __forceinline__ int fmap(float x) {
    int i = __float_as_int(x);
    return (i >= 0) ? i : (i ^ 0x7FFFFFFF);
}
__device__ __forceinline__ float funmap(int i) {
    return __int_as_float((i >= 0) ? i : (i ^ 0x7FFFFFFF));
}

// ---------------------------------------------------------------------------
// main scan: one warp per batch; lane owns ADJACENT states (2l, 2l+1).
//
// Exp-domain chain: P[t] = 2^(A[t] - s) carried directly;
//   P_next = S * G, S = dot(E'[t,:], P), G = 2^(F - s') computed off-chain.
// ALL off-chain operands are >=1 iteration old (redP lagged since R10; the
// feat-max REDUX is now ALSO lagged: computed from fB=feat_{i+1} at iter i,
// consumed at iter i+1). With in-order issue this removes every issue-head
// stall outside the true chain. Output path: (F,S) latched on masked steps;
// A = F + lg2(S) once after the loop.
// ---------------------------------------------------------------------------
__global__ void __launch_bounds__(WARPS_PER_CTA * 32, 1) crf_scan_kernel(
    const float* __restrict__ feats,   // [B, S, T]
    const float* __restrict__ masks,   // [B, S]
    float* __restrict__ out)           // [B, T]
{
    const int wid  = threadIdx.x >> 5;
    const int lane = threadIdx.x & 31;
    const int b    = blockIdx.x * WARPS_PER_CTA + wid;
    const int t0 = 2 * lane, t1 = 2 * lane + 1;

    // per-warp double-buffered P exchange (broadcast reads -> conflict-free)
    __shared__ __align__(16) float vbuf[WARPS_PER_CTA][2][TT];

    // E' rows for this lane's two states, packed as f32x2 pairs over k
    u64 e0[32], e1[32];
    {
        const float4* r0p = (const float4*)(g_E + t0 * TT);
        const float4* r1p = (const float4*)(g_E + t1 * TT);
#pragma unroll
        for (int j = 0; j < 16; j++) {
            float4 a = r0p[j];
            e0[2 * j]     = pk2(a.x, a.y);
            e0[2 * j + 1] = pk2(a.z, a.w);
            float4 c = r1p[j];
            e1[2 * j]     = pk2(c.x, c.y);
            e1[2 * j + 1] = pk2(c.z, c.w);
        }
    }
    const float rm0 = g_rmax[t0];
    const float rm1 = g_rmax[t1];
    const float r20 = rm0 * LOG2E;   // row shift in log2 domain
    const float r21 = rm1 * LOG2E;

    // Rp2 = (max_{t,k} trans + ln 64) * log2e  -- per-step growth bound const.
    const float maxT = funmap(__reduce_max_sync(0xFFFFFFFFu,
                              fmap(fmaxf(rm0, rm1))));
    const float Rp2 = (maxT + LN64) * LOG2E;

    const float* fptr = feats + (long)b * SS * TT;
    const float* mptr = masks + (long)b * SS;

    // alpha0 = feats[:, 0, :]  (log2 domain)
    float2 a00 = *(const float2*)(fptr + t0);
    float A0 = a00.x * LOG2E;
    float A1 = a00.y * LOG2E;

    // output latches: A_out = Flat + lg2(Slat); init encodes alpha0
    float Flat0 = A0, Flat1 = A1;
    float Slat0 = 1.0f, Slat1 = 1.0f;

    // distance-2 feats/mask prefetch (paired LDG.64)
    float2 fA = __ldg((const float2*)(fptr + TT + t0));
    float  mA = __ldg(mptr + 1);
    float2 fB = __ldg((const float2*)(fptr + 2 * TT + t0));
    float  mB = __ldg(mptr + 2);

    // s_1 = exact warp max of A_0 ; P = 2^(A_0 - s_1)
    float sC = funmap(__reduce_max_sync(0xFFFFFFFFu, fmap(fmaxf(A0, A1))));
    float P0 = ex2(A0 - sC);
    float P1 = ex2(A1 - sC);
    // REDUX over positive P: int compare == float compare for x >= 0
    int redP = __reduce_max_sync(0xFFFFFFFFu, __float_as_int(fmaxf(P0, P1)));

    // LAGGED feat-max: mfCur = max feat_1 (from fA), ready before iter 1
    float mfCur = funmap(__reduce_max_sync(0xFFFFFFFFu,
                         fmap(fmaxf(fA.x, fA.y))));

    int p = 0;
#pragma unroll 2
    for (int i = 1; i < SS; i++) {
        // ---- chain head: publish P pair (one STS.64) ---------------------
        float* vb = vbuf[wid][p];
        *(float2*)(vb + t0) = make_float2(P0, P1);
        asm volatile("" ::: "memory");   // compiler barrier: no LDS hoist

        // ---- issue-early, consume-next-iter: feat-max REDUX on fB --------
        int redFN = __reduce_max_sync(0xFFFFFFFFu,
                                      fmap(fmaxf(fB.x, fB.y)));

        // ---- off-chain: shift maintenance (ALL operands >=1 iter old) ----
        // maxA_{i-1} = s_i + log2(max P_i)   (redP from prev iter tail)
        float maxA = sC + lg2(__int_as_float(redP));
        float sN = maxA + fmaxf(0.0f, fmaf(mfCur, LOG2E, Rp2));
        float F0 = fmaf(fA.x, LOG2E, sC + r20);
        float F1 = fmaf(fA.y, LOG2E, sC + r21);
        float G0 = ex2(F0 - sN);
        float G1 = ex2(F1 - sN);
        float H  = ex2(sC - sN);

        // ---- off-chain: prefetch i+2 (clamped, branch-free) --------------
        int ip2 = i + 2; ip2 = (ip2 < SS) ? ip2 : (SS - 1);
        float2 fC = __ldg((const float2*)(fptr + ip2 * TT + t0));
        float  mC = __ldg(mptr + ip2);

        // ---- critical chain: dot S = sum_k E'[t][k] * P[k] ---------------
        const ulonglong2* vv = (const ulonglong2*)vb;
        u64 Aa0 = pk2(0.f, 0.f), Aa1 = Aa0, Bb0 = Aa0, Bb1 = Aa0;
#pragma unroll
        for (int j = 0; j < 16; j++) {
            ulonglong2 q = vv[j];
            Aa0 = fma2(q.x, e0[2 * j],     Aa0);
            Aa1 = fma2(q.y, e0[2 * j + 1], Aa1);
            Bb0 = fma2(q.x, e1[2 * j],     Bb0);
            Bb1 = fma2(q.y, e1[2 * j + 1], Bb1);
        }
        float s0lo, s0hi, s1lo, s1hi;
        upk2(s0lo, s0hi, add2(Aa0, Aa1));
        upk2(s1lo, s1hi, add2(Bb0, Bb1));
        float S0 = s0lo + s0hi;
        float S1 = s1lo + s1hi;

        // ---- chain tail: next P (1 FMUL + select; no MUFU) ---------------
        bool msk = (mA != 0.0f);
        P0 = msk ? S0 * G0 : P0 * H;
        P1 = msk ? S1 * G1 : P1 * H;
        redP = __reduce_max_sync(0xFFFFFFFFu, __float_as_int(fmaxf(P0, P1)));

        // ---- off-chain: latch (F,S) on masked steps (output path) --------
        Flat0 = msk ? F0 : Flat0;
        Flat1 = msk ? F1 : Flat1;
        Slat0 = msk ? S0 : Slat0;
        Slat1 = msk ? S1 : Slat1;

        // rotate shift + prefetch + lagged-max registers
        sC = sN;
        mfCur = funmap(redFN);
        fA = fB; mA = mB;
        fB = fC; mB = mC;
        p ^= 1;
    }

    // A = Flat + lg2(Slat), back to natural log (2 MUFU total, post-loop)
    float2 o;
    o.x = (Flat0 + lg2(Slat0)) * LN2;
    o.y = (Flat1 + lg2(Slat1)) * LN2;
    *(float2*)(out + b * TT + t0) = o;
}

// ---------------------------------------------------------------------------
// launch
// ---------------------------------------------------------------------------
extern "C" void kernel_launch(void* const* d_in, const int* in_sizes, int n_in,
                              void* d_out, int out_size) {
    const float* feats = (const float*)d_in[0];  // [512, 1024, 64]
    const float* masks = (const float*)d_in[1];  // [512, 1024]
    const float* trans = (const float*)d_in[2];  // [64, 64]
    float* out = (float*)d_out;                  // [512, 64]

    crf_prep_kernel<<<TT, TT>>>(trans);
    crf_scan_kernel<<<CTAS, WARPS_PER_CTA * 32>>>(feats, masks, out);
}